// round 11
// baseline (speedup 1.0000x reference)
#include <cuda_runtime.h>
#include <cuda_fp16.h>

#define B    64
#define NB   32    // batch per half
#define NIN  2048
#define DIN  8
#define NOUT 32
#define DOUT 16
#define OD   512   // NOUT*DOUT

// Scratch (device globals: allocation-free at run time)
__device__ __align__(256) __half g_preds[(size_t)B * NIN * OD];  // 2 x 64 MB halves
__device__ float  g_s[B * OD];                     // s accumulator (zero-init; tails re-zero)
__device__ float  g_v[B * OD];                     // current v
__device__ float  g_vsum[B * OD];                  // v1 + v2 (raw3 via linearity)
__device__ int    g_cnt[B];                        // per-b tickets (zero-init; tails reset)

// Shared-memory arena per block: [0,16384) agree reduction, [16384,+) tail flag,
// preds xs reuses [0, 2048).
#define SM_BYTES (16 * 1024 + 64)

// ---- helpers ---------------------------------------------------------------
__device__ __forceinline__ __half2 u32_as_half2(unsigned u) {
    union { unsigned u; __half2 h; } c; c.u = u; return c.h;
}

// ---------------------------------------------------------------------------
// Ticket-gated tail: LAST block for batch b squashes + updates state.
// mode 0: v1 = squash(s/32) -> g_v, g_vsum
// mode 1: v2 = squash(s)    -> g_vsum += v2
// mode 2: v3 = squash(s)    -> outv
// Always: zero g_s[b], reset g_cnt[b].  Requires blockDim.x == 256.
__device__ __forceinline__ void routing_tail(int b, int nblocks, int mode,
                                             float* __restrict__ outv, char* sm) {
    __syncthreads();
    __threadfence();
    int* lastp = (int*)(sm + 16384);
    if (threadIdx.x == 0)
        *lastp = (atomicAdd(&g_cnt[b], 1) == nblocks - 1);
    __syncthreads();
    if (!*lastp) return;
    __threadfence();

    const int t = threadIdx.x;                 // owns od 2t, 2t+1
    float s0 = g_s[b * OD + 2 * t];
    float s1 = g_s[b * OD + 2 * t + 1];
    if (mode == 0) { s0 *= (1.f / NOUT); s1 *= (1.f / NOUT); }
    float sq = s0 * s0 + s1 * s1;              // 8 lanes = one o (16 d)
    sq += __shfl_xor_sync(0xFFFFFFFFu, sq, 1);
    sq += __shfl_xor_sync(0xFFFFFFFFu, sq, 2);
    sq += __shfl_xor_sync(0xFFFFFFFFu, sq, 4);
    float scale = sq / ((1.f + sq) * sqrtf(sq + 1e-7f));
    float v0 = scale * s0, v1 = scale * s1;

    if (mode == 0) {
        g_v[b * OD + 2 * t] = v0;     g_v[b * OD + 2 * t + 1] = v1;
        g_vsum[b * OD + 2 * t] = v0;  g_vsum[b * OD + 2 * t + 1] = v1;
    } else if (mode == 1) {
        g_vsum[b * OD + 2 * t] += v0; g_vsum[b * OD + 2 * t + 1] += v1;
    } else {
        outv[b * OD + 2 * t] = v0;    outv[b * OD + 2 * t + 1] = v1;
    }
    g_s[b * OD + 2 * t] = 0.f;
    g_s[b * OD + 2 * t + 1] = 0.f;
    if (t == 0) g_cnt[b] = 0;
}

// ---------------------------------------------------------------------------
// preds role: block = 2 consecutive n (128 threads each sub-block).
// preds[b,n,od] = sum_i W[n,od,i] * x[b,n,i] for b in [B0, B0+NB)
__device__ __forceinline__ void do_preds(int pidx, int B0,
                                         const float* __restrict__ x,
                                         const float* __restrict__ W_, char* sm) {
    const int t = threadIdx.x;
    const int sub = t >> 7, tt = t & 127;
    const int n = pidx * 2 + sub;
    float* xs = (float*)sm + sub * (NB * DIN);   // 256 floats per sub-block
    if (tt < 64) {
        int b = tt >> 1, h = tt & 1;
        float4 xv = *(const float4*)(x + ((B0 + b) * NIN + n) * DIN + h * 4);
        *(float4*)(xs + b * DIN + h * 4) = xv;
    }
    __syncthreads();

    const float* Wn = W_ + (size_t)n * (OD * DIN) + tt * 32;  // 4 od * 8 i
    float4 w[8];
#pragma unroll
    for (int j = 0; j < 8; j++) w[j] = ((const float4*)Wn)[j];

    __half* outp = g_preds + (size_t)(B0 * NIN + n) * OD + tt * 4;
#pragma unroll 4
    for (int b = 0; b < NB; b++) {
        float4 x0 = *(float4*)(xs + b * 8);
        float4 x1 = *(float4*)(xs + b * 8 + 4);
        float r0 = w[0].x*x0.x + w[0].y*x0.y + w[0].z*x0.z + w[0].w*x0.w
                 + w[1].x*x1.x + w[1].y*x1.y + w[1].z*x1.z + w[1].w*x1.w;
        float r1 = w[2].x*x0.x + w[2].y*x0.y + w[2].z*x0.z + w[2].w*x0.w
                 + w[3].x*x1.x + w[3].y*x1.y + w[3].z*x1.z + w[3].w*x1.w;
        float r2 = w[4].x*x0.x + w[4].y*x0.y + w[4].z*x0.z + w[4].w*x0.w
                 + w[5].x*x1.x + w[5].y*x1.y + w[5].z*x1.z + w[5].w*x1.w;
        float r3 = w[6].x*x0.x + w[6].y*x0.y + w[6].z*x0.z + w[6].w*x0.w
                 + w[7].x*x1.x + w[7].y*x1.y + w[7].z*x1.z + w[7].w*x1.w;
        union { uint2 u; __half2 h[2]; } pk;
        pk.h[0] = __floats2half2_rn(r0, r1);
        pk.h[1] = __floats2half2_rn(r2, r3);
        *(uint2*)(outp + (size_t)b * NIN * OD) = pk.u;
    }
}

// ---------------------------------------------------------------------------
// s1 role: s1[b,od] = sum_n preds[b,n,od]; tail squashes (/32).
__device__ __forceinline__ void do_s1(int sidx, int B0, char* sm) {
    const int c = sidx & 15, b = B0 + (sidx >> 4);
    const int t = threadIdx.x;  // 0..255
    const unsigned* p = (const unsigned*)g_preds
                      + (size_t)(b * NIN + c * 128) * (OD / 2) + t;
    float acx = 0.f, acy = 0.f;
#pragma unroll 8
    for (int n = 0; n < 128; n++) {
        float2 f = __half22float2(u32_as_half2(__ldg(p + (size_t)n * (OD / 2))));
        acx += f.x; acy += f.y;
    }
    atomicAdd(&g_s[b * OD + 2 * t],     acx);
    atomicAdd(&g_s[b * OD + 2 * t + 1], acy);
    routing_tail(b, 16, 0, nullptr, sm);
}

// ---------------------------------------------------------------------------
// agree role: fused agreement + batched softmax + weighted-s + tail squash.
// aidx in [0, 1024): chunk = aidx&31 (64 n), b = B0 + (aidx>>5).
// PASS 0: raw = preds.v1 (g_v), tail mode 1.  PASS 1: raw = preds.(v1+v2)
// (g_vsum), rw -> out_rw, tail mode 2 (v3 -> outv).
template <int PASS>
__device__ __forceinline__ void do_agree(int aidx, int B0,
                                         float* __restrict__ out_rw,
                                         float* __restrict__ outv, char* sm) {
    const int b = B0 + (aidx >> 5);
    const int warp = threadIdx.x >> 5, lane = threadIdx.x & 31;
    const int n0 = (aidx & 31) * 64 + warp * 8;

    const float* vin = (PASS == 0 ? g_v : g_vsum) + b * OD + lane * 16;
    float vr[16];
#pragma unroll
    for (int j = 0; j < 4; j++) *(float4*)(vr + 4 * j) = ((const float4*)vin)[j];

    const uint4* pbase = (const uint4*)(g_preds + (size_t)(b * NIN + n0) * OD) + lane * 2;
    const int row_u4 = OD / 8;   // 64 uint4 per n-row

    // ---- Phase A: logits + exp for 8 rows (depth-2 load pipeline) ----
    float e[8];
    uint4 c0 = __ldg(pbase), c1 = __ldg(pbase + 1);
#pragma unroll
    for (int k = 0; k < 8; k++) {
        uint4 f0 = c0, f1 = c1;
        if (k < 7) {
            c0 = __ldg(pbase + (k + 1) * row_u4);
            c1 = __ldg(pbase + (k + 1) * row_u4 + 1);
        }
        union { uint4 u; __half2 h[4]; } a0, a1;
        a0.u = f0; a1.u = f1;
        float a = 0.f;
#pragma unroll
        for (int j = 0; j < 4; j++) {
            float2 g0 = __half22float2(a0.h[j]);
            float2 g1 = __half22float2(a1.h[j]);
            a = fmaf(g0.x, vr[2 * j], a);
            a = fmaf(g0.y, vr[2 * j + 1], a);
            a = fmaf(g1.x, vr[8 + 2 * j], a);
            a = fmaf(g1.y, vr[8 + 2 * j + 1], a);
        }
        e[k] = __expf(a);     // |logit| <= ~6, no max-shift needed
    }

    // ---- Phase B: 8 interleaved 32-lane sum reductions ----
    float es[8];
#pragma unroll
    for (int k = 0; k < 8; k++) es[k] = e[k];
#pragma unroll
    for (int s = 16; s; s >>= 1) {
#pragma unroll
        for (int k = 0; k < 8; k++)
            es[k] += __shfl_xor_sync(0xFFFFFFFFu, es[k], s);
    }
#pragma unroll
    for (int k = 0; k < 8; k++) e[k] = __fdividef(e[k], es[k]);   // rw

    // ---- Phase C: re-read rows (L1-resident), accumulate s; emit rw ----
    float sp[16];
#pragma unroll
    for (int d = 0; d < 16; d++) sp[d] = 0.f;
    c0 = __ldg(pbase); c1 = __ldg(pbase + 1);
#pragma unroll
    for (int k = 0; k < 8; k++) {
        uint4 f0 = c0, f1 = c1;
        if (k < 7) {
            c0 = __ldg(pbase + (k + 1) * row_u4);
            c1 = __ldg(pbase + (k + 1) * row_u4 + 1);
        }
        union { uint4 u; __half2 h[4]; } a0, a1;
        a0.u = f0; a1.u = f1;
        const float rw = e[k];
#pragma unroll
        for (int j = 0; j < 4; j++) {
            float2 g0 = __half22float2(a0.h[j]);
            float2 g1 = __half22float2(a1.h[j]);
            sp[2 * j]      = fmaf(rw, g0.x, sp[2 * j]);
            sp[2 * j + 1]  = fmaf(rw, g0.y, sp[2 * j + 1]);
            sp[8 + 2 * j]     = fmaf(rw, g1.x, sp[8 + 2 * j]);
            sp[8 + 2 * j + 1] = fmaf(rw, g1.y, sp[8 + 2 * j + 1]);
        }
        if (PASS == 1)
            out_rw[(b * NIN + n0 + k) * NOUT + lane] = rw;
    }

    // block-level reduction of s partials, then one atomicAdd per od
    float (*red)[OD] = (float(*)[OD])sm;
#pragma unroll
    for (int j = 0; j < 4; j++)
        *(float4*)(&red[warp][lane * 16 + 4 * j]) = *(float4*)(sp + 4 * j);
    __syncthreads();
    for (int j = threadIdx.x; j < OD; j += 256) {
        float a = 0.f;
#pragma unroll
        for (int w = 0; w < 8; w++) a += red[w][j];
        atomicAdd(&g_s[b * OD + j], a);
    }

    routing_tail(b, 32, PASS == 0 ? 1 : 2, outv, sm);
}

// ---------------------------------------------------------------------------
// Wave kernels: co-schedule independent stages of the two half-pipelines.
__global__ __launch_bounds__(256, 4)
void k_w1(const float* __restrict__ x, const float* __restrict__ W_) {
    __shared__ __align__(16) char sm[SM_BYTES];
    do_preds(blockIdx.x, 0, x, W_, sm);                       // P half0
}

__global__ __launch_bounds__(256, 4)
void k_w2(const float* __restrict__ x, const float* __restrict__ W_) {
    __shared__ __align__(16) char sm[SM_BYTES];
    const int bid = blockIdx.x;          // 1536 blocks, striped 2:1
    const int m = bid % 3;
    if (m != 2) do_preds((bid / 3) * 2 + m, NB, x, W_, sm);   // P half1 (1024)
    else        do_s1(bid / 3, 0, sm);                        // S half0 (512)
}

__global__ __launch_bounds__(256, 4)
void k_w3() {
    __shared__ __align__(16) char sm[SM_BYTES];
    const int bid = blockIdx.x;          // 1536 blocks, striped 2:1
    const int m = bid % 3;
    if (m != 2) do_agree<0>((bid / 3) * 2 + m, 0, nullptr, nullptr, sm);  // A half0
    else        do_s1(bid / 3, NB, sm);                                    // S half1
}

__global__ __launch_bounds__(256, 4)
void k_w4(float* __restrict__ out_rw, float* __restrict__ outv) {
    __shared__ __align__(16) char sm[SM_BYTES];
    const int bid = blockIdx.x;          // 2048 blocks, alternating halves
    if ((bid & 1) == 0) do_agree<1>(bid >> 1, 0, out_rw, outv, sm);       // A' half0
    else                do_agree<0>(bid >> 1, NB, nullptr, nullptr, sm);  // A half1
}

__global__ __launch_bounds__(256, 4)
void k_w5(float* __restrict__ out_rw, float* __restrict__ outv) {
    __shared__ __align__(16) char sm[SM_BYTES];
    do_agree<1>(blockIdx.x, NB, out_rw, outv, sm);                        // A' half1
}

// ---------------------------------------------------------------------------
extern "C" void kernel_launch(void* const* d_in, const int* in_sizes, int n_in,
                              void* d_out, int out_size) {
    (void)in_sizes; (void)n_in; (void)out_size;
    const float* x = (const float*)d_in[0];   // [64, 2048, 8]
    const float* W = (const float*)d_in[1];   // [2048, 32, 16, 8]
    float* out = (float*)d_out;               // v (32768 floats) then rw (4194304)
    float* out_rw = out + B * OD;

    k_w1<<<1024, 256>>>(x, W);                // P0
    k_w2<<<1536, 256>>>(x, W);                // P1 || S0
    k_w3<<<1536, 256>>>();                    // A0 || S1
    k_w4<<<2048, 256>>>(out_rw, out);         // A0' || A1
    k_w5<<<1024, 256>>>(out_rw, out);         // A1'
}

// round 13
// speedup vs baseline: 1.4085x; 1.4085x over previous
#include <cuda_runtime.h>
#include <cuda_fp16.h>

#define B    64
#define NB   32    // batch per half
#define NIN  2048
#define DIN  8
#define NOUT 32
#define DOUT 16
#define OD   512   // NOUT*DOUT

// Scratch (device globals: allocation-free at run time)
__device__ __align__(256) __half g_preds[(size_t)B * NIN * OD];  // 2 x 64 MB halves
__device__ float  g_s[B * OD];                     // s accumulator (zero-init; tails re-zero)
__device__ float  g_v[B * OD];                     // current v
__device__ float  g_vsum[B * OD];                  // v1 + v2 (raw3 via linearity)
__device__ int    g_cnt[B];                        // per-b tickets (zero-init; tails reset)

// ---- helpers ---------------------------------------------------------------
__device__ __forceinline__ __half2 u32_as_half2(unsigned u) {
    union { unsigned u; __half2 h; } c; c.u = u; return c.h;
}
__device__ __forceinline__ unsigned long long pack2(float lo, float hi) {
    union { float2 f; unsigned long long u; } c;
    c.f = make_float2(lo, hi);
    return c.u;
}
__device__ __forceinline__ float2 unpack2(unsigned long long u) {
    union { unsigned long long u; float2 f; } c;
    c.u = u;
    return c.f;
}
// Packed dual-FMA (sm_100+): d.lo = a.lo*b.lo + c.lo ; d.hi likewise.
#define FMA_F32X2(d, a, b, c) \
    asm("fma.rn.f32x2 %0, %1, %2, %3;" : "=l"(d) : "l"(a), "l"(b), "l"(c))

// ---------------------------------------------------------------------------
// preds[b,n,od] = sum_i W[n,od,i] * x[b,n,i] for b in [B0, B0+NB)
// One block per n; 128 threads; 4 od/thread. f32x2 packed math: weights for
// (od0,od1) and (od2,od3) are packed into 64-bit pairs once; x is staged in
// smem duplicated as (x,x) so each fma.rn.f32x2 does 2 FMAs.
template <int B0>
__global__ __launch_bounds__(128, 6)
void k_preds(const float* __restrict__ x, const float* __restrict__ W) {
    const int n = blockIdx.x;
    const int t = threadIdx.x;                 // 0..127
    __shared__ float2 xs2[NB * DIN];           // (x,x) duplicated pairs
    if (t < 64) {
        int b = t >> 1, h = t & 1;
        float4 xv = *(const float4*)(x + ((B0 + b) * NIN + n) * DIN + h * 4);
        xs2[b * DIN + h * 4 + 0] = make_float2(xv.x, xv.x);
        xs2[b * DIN + h * 4 + 1] = make_float2(xv.y, xv.y);
        xs2[b * DIN + h * 4 + 2] = make_float2(xv.z, xv.z);
        xs2[b * DIN + h * 4 + 3] = make_float2(xv.w, xv.w);
    }
    __syncthreads();

    const float* Wn = W + (size_t)n * (NOUT * DOUT * DIN) + t * 32;  // 4 od * 8 i
    float4 w[8];
#pragma unroll
    for (int j = 0; j < 8; j++) w[j] = ((const float4*)Wn)[j];

    // Pack weight pairs: p01[i] = (W[od0][i], W[od1][i]), p23[i] = (od2, od3).
    unsigned long long p01[8], p23[8];
#pragma unroll
    for (int q = 0; q < 2; q++) {
        const float* w0 = (const float*)&w[q];      // od0, i = 4q..4q+3
        const float* w1 = (const float*)&w[2 + q];  // od1
        const float* w2 = (const float*)&w[4 + q];  // od2
        const float* w3 = (const float*)&w[6 + q];  // od3
#pragma unroll
        for (int r = 0; r < 4; r++) {
            p01[q * 4 + r] = pack2(w0[r], w1[r]);
            p23[q * 4 + r] = pack2(w2[r], w3[r]);
        }
    }

    __half* outp = g_preds + (size_t)(B0 * NIN + n) * OD + t * 4;
#pragma unroll 4
    for (int b = 0; b < NB; b++) {
        const unsigned long long* xd = (const unsigned long long*)(xs2 + b * DIN);
        unsigned long long acc01 = 0ULL, acc23 = 0ULL;   // (0.f, 0.f)
#pragma unroll
        for (int j = 0; j < 8; j++) {
            unsigned long long xj = xd[j];
            FMA_F32X2(acc01, p01[j], xj, acc01);
            FMA_F32X2(acc23, p23[j], xj, acc23);
        }
        float2 r01 = unpack2(acc01);
        float2 r23 = unpack2(acc23);
        union { uint2 u; __half2 h[2]; } pk;
        pk.h[0] = __floats2half2_rn(r01.x, r01.y);
        pk.h[1] = __floats2half2_rn(r23.x, r23.y);
        *(uint2*)(outp + (size_t)b * NIN * OD) = pk.u;
    }
}

// ---------------------------------------------------------------------------
// Ticket-gated tail: LAST block for batch b squashes + updates state.
// mode 0: v1 = squash(s/32) -> g_v, g_vsum
// mode 1: v2 = squash(s)    -> g_vsum += v2
// mode 2: v3 = squash(s)    -> outv
// Always: zero g_s[b], reset g_cnt[b].  Requires blockDim.x == 256.
__device__ __forceinline__ void routing_tail(int b, int nblocks, int mode,
                                             float* __restrict__ outv) {
    __syncthreads();
    __threadfence();
    __shared__ int last;
    if (threadIdx.x == 0)
        last = (atomicAdd(&g_cnt[b], 1) == nblocks - 1);
    __syncthreads();
    if (!last) return;
    __threadfence();

    const int t = threadIdx.x;                 // owns od 2t, 2t+1
    float s0 = g_s[b * OD + 2 * t];
    float s1 = g_s[b * OD + 2 * t + 1];
    if (mode == 0) { s0 *= (1.f / NOUT); s1 *= (1.f / NOUT); }
    float sq = s0 * s0 + s1 * s1;              // 8 lanes = one o (16 d)
    sq += __shfl_xor_sync(0xFFFFFFFFu, sq, 1);
    sq += __shfl_xor_sync(0xFFFFFFFFu, sq, 2);
    sq += __shfl_xor_sync(0xFFFFFFFFu, sq, 4);
    float scale = sq / ((1.f + sq) * sqrtf(sq + 1e-7f));
    float v0 = scale * s0, v1 = scale * s1;

    if (mode == 0) {
        g_v[b * OD + 2 * t] = v0;     g_v[b * OD + 2 * t + 1] = v1;
        g_vsum[b * OD + 2 * t] = v0;  g_vsum[b * OD + 2 * t + 1] = v1;
    } else if (mode == 1) {
        g_vsum[b * OD + 2 * t] += v0; g_vsum[b * OD + 2 * t + 1] += v1;
    } else {
        outv[b * OD + 2 * t] = v0;    outv[b * OD + 2 * t + 1] = v1;
    }
    g_s[b * OD + 2 * t] = 0.f;
    g_s[b * OD + 2 * t + 1] = 0.f;
    if (t == 0) g_cnt[b] = 0;
}

// ---------------------------------------------------------------------------
// Iteration 1 (per half): s1[b,od] = sum_n preds[b,n,od]; tail squashes (/32).
template <int B0>
__global__ __launch_bounds__(256, 8)
void k_s1() {
    const int b = B0 + blockIdx.y, c = blockIdx.x;
    const int t = threadIdx.x;  // 0..255
    const unsigned* p = (const unsigned*)g_preds
                      + (size_t)(b * NIN + c * 128) * (OD / 2) + t;
    float acx = 0.f, acy = 0.f;
#pragma unroll 8
    for (int n = 0; n < 128; n++) {
        float2 f = __half22float2(u32_as_half2(__ldg(p + (size_t)n * (OD / 2))));
        acx += f.x; acy += f.y;
    }
    atomicAdd(&g_s[b * OD + 2 * t],     acx);
    atomicAdd(&g_s[b * OD + 2 * t + 1], acy);
    routing_tail(b, 16, 0, nullptr);
}

// ---------------------------------------------------------------------------
// Fused agreement + BATCHED softmax + weighted-s accumulation + tail squash.
// grid (32 n-chunks, NB b); 8 warps; warp handles 8 n; lane = o.
// Phase A: stream rows, logits (4-way split accumulator) + exp.
// Phase B: 8 interleaved butterfly reductions.  Phase C: re-read rows
// (L1-hot), accumulate rw*p.
template <int PASS, int B0>
__global__ __launch_bounds__(256, 3)
void k_agree(float* __restrict__ out_rw, float* __restrict__ outv) {
    const int b = B0 + blockIdx.y;
    const int warp = threadIdx.x >> 5, lane = threadIdx.x & 31;
    const int n0 = blockIdx.x * 64 + warp * 8;

    const float* vin = (PASS == 0 ? g_v : g_vsum) + b * OD + lane * 16;
    float vr[16];
#pragma unroll
    for (int j = 0; j < 4; j++) *(float4*)(vr + 4 * j) = ((const float4*)vin)[j];

    const uint4* pbase = (const uint4*)(g_preds + (size_t)(b * NIN + n0) * OD) + lane * 2;
    const int row_u4 = OD / 8;   // 64 uint4 per n-row

    // ---- Phase A: logits + exp for 8 rows (depth-2 load pipeline) ----
    float e[8];
    uint4 c0 = __ldg(pbase), c1 = __ldg(pbase + 1);
#pragma unroll
    for (int k = 0; k < 8; k++) {
        uint4 f0 = c0, f1 = c1;
        if (k < 7) {
            c0 = __ldg(pbase + (k + 1) * row_u4);
            c1 = __ldg(pbase + (k + 1) * row_u4 + 1);
        }
        union { uint4 u; __half2 h[4]; } a0, a1;
        a0.u = f0; a1.u = f1;
        // 4-way split accumulator: serial depth 4 FMA + add tree (was 16 FMA).
        float t0 = 0.f, t1 = 0.f, t2 = 0.f, t3 = 0.f;
#pragma unroll
        for (int j = 0; j < 4; j++) {
            float2 g0 = __half22float2(a0.h[j]);
            float2 g1 = __half22float2(a1.h[j]);
            t0 = fmaf(g0.x, vr[2 * j], t0);
            t1 = fmaf(g0.y, vr[2 * j + 1], t1);
            t2 = fmaf(g1.x, vr[8 + 2 * j], t2);
            t3 = fmaf(g1.y, vr[8 + 2 * j + 1], t3);
        }
        e[k] = __expf((t0 + t1) + (t2 + t3));   // |logit| <= ~6, no max-shift
    }

    // ---- Phase B: 8 interleaved 32-lane sum reductions ----
    float es[8];
#pragma unroll
    for (int k = 0; k < 8; k++) es[k] = e[k];
#pragma unroll
    for (int s = 16; s; s >>= 1) {
#pragma unroll
        for (int k = 0; k < 8; k++)
            es[k] += __shfl_xor_sync(0xFFFFFFFFu, es[k], s);
    }
#pragma unroll
    for (int k = 0; k < 8; k++) e[k] = __fdividef(e[k], es[k]);   // rw

    // ---- Phase C: re-read rows (L1-resident), accumulate s; emit rw ----
    float sp[16];
#pragma unroll
    for (int d = 0; d < 16; d++) sp[d] = 0.f;
    c0 = __ldg(pbase); c1 = __ldg(pbase + 1);
#pragma unroll
    for (int k = 0; k < 8; k++) {
        uint4 f0 = c0, f1 = c1;
        if (k < 7) {
            c0 = __ldg(pbase + (k + 1) * row_u4);
            c1 = __ldg(pbase + (k + 1) * row_u4 + 1);
        }
        union { uint4 u; __half2 h[4]; } a0, a1;
        a0.u = f0; a1.u = f1;
        const float rw = e[k];
#pragma unroll
        for (int j = 0; j < 4; j++) {
            float2 g0 = __half22float2(a0.h[j]);
            float2 g1 = __half22float2(a1.h[j]);
            sp[2 * j]      = fmaf(rw, g0.x, sp[2 * j]);
            sp[2 * j + 1]  = fmaf(rw, g0.y, sp[2 * j + 1]);
            sp[8 + 2 * j]     = fmaf(rw, g1.x, sp[8 + 2 * j]);
            sp[8 + 2 * j + 1] = fmaf(rw, g1.y, sp[8 + 2 * j + 1]);
        }
        if (PASS == 1)
            out_rw[(b * NIN + n0 + k) * NOUT + lane] = rw;
    }

    // block-level reduction of s partials, then one atomicAdd per od
    __shared__ float red[8][OD];
#pragma unroll
    for (int j = 0; j < 4; j++)
        *(float4*)(&red[warp][lane * 16 + 4 * j]) = *(float4*)(sp + 4 * j);
    __syncthreads();
    for (int j = threadIdx.x; j < OD; j += 256) {
        float a = 0.f;
#pragma unroll
        for (int w = 0; w < 8; w++) a += red[w][j];
        atomicAdd(&g_s[b * OD + j], a);
    }

    routing_tail(b, 32, PASS == 0 ? 1 : 2, outv);
}

// ---------------------------------------------------------------------------
extern "C" void kernel_launch(void* const* d_in, const int* in_sizes, int n_in,
                              void* d_out, int out_size) {
    (void)in_sizes; (void)n_in; (void)out_size;
    const float* x = (const float*)d_in[0];   // [64, 2048, 8]
    const float* W = (const float*)d_in[1];   // [2048, 32, 16, 8]
    float* out = (float*)d_out;               // v (32768 floats) then rw (4194304)
    float* out_rw = out + B * OD;

    // Half 0
    k_preds<0><<<NIN, 128>>>(x, W);
    k_s1<0><<<dim3(16, NB), 256>>>();
    k_agree<0, 0><<<dim3(32, NB), 256>>>(nullptr, nullptr);
    k_agree<1, 0><<<dim3(32, NB), 256>>>(out_rw, out);

    // Half 1
    k_preds<NB><<<NIN, 128>>>(x, W);
    k_s1<NB><<<dim3(16, NB), 256>>>();
    k_agree<0, NB><<<dim3(32, NB), 256>>>(nullptr, nullptr);
    k_agree<1, NB><<<dim3(32, NB), 256>>>(out_rw, out);
}